// round 1
// baseline (speedup 1.0000x reference)
#include <cuda_runtime.h>
#include <math.h>

#define Xn 262144
#define Bn 64
#define Kf 8
#define Hn 256
#define NTOK (Bn * Kf)   // 512 tokens

// ---------------- device scratch (static, no allocs) ----------------
__device__ float g_h[NTOK * Hn];        // 512x256
__device__ float g_z[NTOK * Hn];        // 512x256
__device__ float g_zz[NTOK * 2 * Hn];   // 512x512
__device__ float g_a1[NTOK * 128];      // 512x128
__device__ float g_uL[NTOK], g_uR[NTOK], g_fcv[NTOK], g_val[NTOK];
__device__ int   g_count[Bn];

__device__ __forceinline__ float gelu_f(float v) {
    return 0.5f * v * (1.0f + erff(v * 0.70710678118654752f));
}

// ---------------- zero counters ----------------
__global__ void zero_counts() {
    if (threadIdx.x < Bn) g_count[threadIdx.x] = 0;
}

// ---------------- find first-8 disc indices per batch ----------------
__global__ void find_fronts(const float* __restrict__ x) {
    int b = blockIdx.x;
    const float* d = x + (size_t)b * 2 * Xn;
    const float* c = d + Xn;

    __shared__ unsigned wmask[8], vmask[8];
    __shared__ int s_idx[8], s_non[8];
    __shared__ int s_nd, s_nn, s_done;
    if (threadIdx.x == 0) { s_nd = 0; s_nn = 0; s_done = 0; }
    __syncthreads();

    for (int base = 0; base < Xn - 1; base += 256) {
        int i = base + threadIdx.x;
        bool valid = (i < Xn - 1);
        bool disc = false;
        if (valid) disc = fabsf(d[i] - d[i + 1]) > 1e-6f;
        unsigned m  = __ballot_sync(0xffffffffu, disc);
        unsigned vm = __ballot_sync(0xffffffffu, valid);
        if ((threadIdx.x & 31) == 0) {
            wmask[threadIdx.x >> 5] = m;
            vmask[threadIdx.x >> 5] = vm;
        }
        __syncthreads();
        if (threadIdx.x == 0) {
            for (int w = 0; w < 8 && s_nd < 8; w++) {
                unsigned mm = wmask[w], vv = vmask[w];
                int ib = base + w * 32;
                while (vv) {
                    int lane = __ffs(vv) - 1;
                    vv &= vv - 1;
                    int idx = ib + lane;
                    if ((mm >> lane) & 1u) {
                        if (s_nd < 8) s_idx[s_nd++] = idx;
                        if (s_nd >= 8) break;
                    } else {
                        if (s_nn < 8) s_non[s_nn++] = idx;
                    }
                }
            }
            if (s_nd >= 8) s_done = 1;
        }
        __syncthreads();
        if (s_done) break;
    }

    if (threadIdx.x < 8) {
        int k = threadIdx.x;
        int nd = s_nd;
        int i; float vflag;
        if (k < nd) { i = s_idx[k]; vflag = 1.0f; }
        else        { i = s_non[k - nd]; vflag = 0.0f; }
        int t = b * 8 + k;
        g_uL[t]  = d[i];
        g_uR[t]  = d[i + 1];
        g_fcv[t] = 0.5f * (c[i] + c[i + 1]);
        g_val[t] = vflag;
    }
}

// ---------------- count discontinuities (full 64MB scan) ----------------
__global__ void count_kernel(const float* __restrict__ x) {
    int b = blockIdx.y;
    const float* d = x + (size_t)b * 2 * Xn;
    int t = blockIdx.x * blockDim.x + threadIdx.x;  // 0..32767
    int j0 = t * 8;
    int cnt = 0;
    if (j0 < Xn - 1) {
        float4 v0 = *(const float4*)(d + j0);
        float4 v1 = *(const float4*)(d + j0 + 4);
        float a[9];
        a[0] = v0.x; a[1] = v0.y; a[2] = v0.z; a[3] = v0.w;
        a[4] = v1.x; a[5] = v1.y; a[6] = v1.z; a[7] = v1.w;
        a[8] = (j0 + 8 <= Xn - 1) ? d[j0 + 8] : 0.0f;
        #pragma unroll
        for (int u = 0; u < 8; u++)
            if (j0 + u < Xn - 1 && fabsf(a[u] - a[u + 1]) > 1e-6f) cnt++;
    }
    #pragma unroll
    for (int o = 16; o; o >>= 1) cnt += __shfl_down_sync(0xffffffffu, cnt, o);
    __shared__ int ws[8];
    if ((threadIdx.x & 31) == 0) ws[threadIdx.x >> 5] = cnt;
    __syncthreads();
    if (threadIdx.x == 0) {
        int s = 0;
        #pragma unroll
        for (int w = 0; w < 8; w++) s += ws[w];
        atomicAdd(&g_count[b], s);
    }
}

// ---------------- block mean/var over 256 values ----------------
__device__ __forceinline__ void blk_meanvar(float v, float& mu, float& var, float* sbuf) {
    float s1 = v, s2 = v * v;
    #pragma unroll
    for (int o = 16; o; o >>= 1) {
        s1 += __shfl_xor_sync(0xffffffffu, s1, o);
        s2 += __shfl_xor_sync(0xffffffffu, s2, o);
    }
    int w = threadIdx.x >> 5;
    if ((threadIdx.x & 31) == 0) { sbuf[w] = s1; sbuf[8 + w] = s2; }
    __syncthreads();
    if (threadIdx.x < 32) {
        float a  = (threadIdx.x < 8) ? sbuf[threadIdx.x] : 0.0f;
        float bq = (threadIdx.x < 8) ? sbuf[8 + threadIdx.x] : 0.0f;
        #pragma unroll
        for (int o = 4; o; o >>= 1) {
            a  += __shfl_xor_sync(0xffffffffu, a, o);
            bq += __shfl_xor_sync(0xffffffffu, bq, o);
        }
        if (threadIdx.x == 0) { sbuf[16] = a; sbuf[17] = bq; }
    }
    __syncthreads();
    float s1t = sbuf[16], s2t = sbuf[17];
    mu = s1t * (1.0f / 256.0f);
    var = fmaxf(s2t * (1.0f / 256.0f) - mu * mu, 0.0f);
}

// ---------------- input layer: feats @ w_in + LN + gelu -> g_h ----------------
__global__ void mlp_in(const float* __restrict__ w_in, const float* __restrict__ b_in,
                       const float* __restrict__ lng, const float* __restrict__ lnb) {
    __shared__ float sbuf[18];
    int t = blockIdx.x;
    int n = threadIdx.x;
    float uLv = g_uL[t], uRv = g_uR[t];
    float diff = uLv - uRv;
    float f0 = uLv, f1 = uRv, f2 = diff, f3 = fabsf(diff);
    float f4 = (uLv + uRv) * 0.5f;
    float f5 = (diff > 0.0f) ? 1.0f : ((diff < 0.0f) ? -1.0f : 0.0f);
    float pre = b_in[n]
        + f0 * w_in[0 * Hn + n] + f1 * w_in[1 * Hn + n] + f2 * w_in[2 * Hn + n]
        + f3 * w_in[3 * Hn + n] + f4 * w_in[4 * Hn + n] + f5 * w_in[5 * Hn + n];
    float mu, var;
    blk_meanvar(pre, mu, var, sbuf);
    float v = (pre - mu) * rsqrtf(var + 1e-5f) * lng[n] + lnb[n];
    g_h[t * Hn + n] = gelu_f(v);
}

// ---------------- layernorm: g_h -> g_z ----------------
__global__ void ln_kernel(const float* __restrict__ in, const float* __restrict__ g,
                          const float* __restrict__ bta, float* __restrict__ out) {
    __shared__ float sbuf[18];
    int t = blockIdx.x;
    int n = threadIdx.x;
    float v = in[t * Hn + n];
    float mu, var;
    blk_meanvar(v, mu, var, sbuf);
    out[t * Hn + n] = (v - mu) * rsqrtf(var + 1e-5f) * g[n] + bta[n];
}

// ---------------- tiled fp32 GEMM: C = act(A @ B + bias) [+ res] ----------------
template<int BM, int BN, int BK, int TM, int TN, bool GELU, bool RES>
__global__ void gemm_k(const float* __restrict__ A, const float* __restrict__ Bw,
                       const float* __restrict__ bias, float* __restrict__ C,
                       const float* __restrict__ Rs, int M, int N, int K) {
    constexpr int BNT = BN / TN;
    constexpr int BMT = BM / TM;
    constexpr int THREADS = BNT * BMT;
    __shared__ float As[BM][BK + 1];
    __shared__ float Bs[BK][BN + 1];
    int tid = threadIdx.x;
    int tx = tid % BNT, ty = tid / BNT;
    int row0 = blockIdx.y * BM, col0 = blockIdx.x * BN;
    float acc[TM][TN];
    #pragma unroll
    for (int i = 0; i < TM; i++)
        #pragma unroll
        for (int j = 0; j < TN; j++) acc[i][j] = 0.0f;

    for (int k0 = 0; k0 < K; k0 += BK) {
        #pragma unroll
        for (int i = tid; i < BM * BK; i += THREADS) {
            int r = i / BK, c = i % BK;
            As[r][c] = A[(size_t)(row0 + r) * K + k0 + c];
        }
        #pragma unroll
        for (int i = tid; i < BK * BN; i += THREADS) {
            int r = i / BN, c = i % BN;
            Bs[r][c] = Bw[(size_t)(k0 + r) * N + col0 + c];
        }
        __syncthreads();
        #pragma unroll
        for (int kk = 0; kk < BK; kk++) {
            float a[TM], b[TN];
            #pragma unroll
            for (int i = 0; i < TM; i++) a[i] = As[ty * TM + i][kk];
            #pragma unroll
            for (int j = 0; j < TN; j++) b[j] = Bs[kk][tx * TN + j];
            #pragma unroll
            for (int i = 0; i < TM; i++)
                #pragma unroll
                for (int j = 0; j < TN; j++) acc[i][j] = fmaf(a[i], b[j], acc[i][j]);
        }
        __syncthreads();
    }

    #pragma unroll
    for (int i = 0; i < TM; i++) {
        int r = row0 + ty * TM + i;
        #pragma unroll
        for (int j = 0; j < TN; j++) {
            int c = col0 + tx * TN + j;
            float v = acc[i][j] + bias[c];
            if (GELU) v = gelu_f(v);
            if (RES) v += Rs[(size_t)r * N + c];
            C[(size_t)r * N + c] = v;
        }
    }
}

// ---------------- speed head: a1 @ out_w2 + out_b2 -> d_out (transposed) ----------------
__global__ void speed_kernel(const float* __restrict__ w2, const float* __restrict__ b2,
                             float* __restrict__ out) {
    int gid = blockIdx.x * blockDim.x + threadIdx.x;
    if (gid >= NTOK * 2) return;
    int t = gid >> 1, cc = gid & 1;
    float acc = b2[cc];
    const float* a = g_a1 + t * 128;
    #pragma unroll 16
    for (int j = 0; j < 128; j++) acc = fmaf(a[j], w2[j * 2 + cc], acc);
    int b = t >> 3, k = t & 7;
    out[b * 48 + cc * 8 + k] = acc;
}

// ---------------- assemble uL/uR/fc/valid channels + counts ----------------
__global__ void assemble(float* __restrict__ out) {
    int gid = threadIdx.x;
    if (gid < NTOK) {
        int b = gid >> 3, k = gid & 7;
        int base = b * 48;
        out[base + 16 + k] = g_uL[gid];
        out[base + 24 + k] = g_uR[gid];
        out[base + 32 + k] = g_fcv[gid];
        out[base + 40 + k] = g_val[gid];
    }
    if (gid < Bn) out[Bn * 48 + gid] = (float)g_count[gid];
}

// ---------------- launch ----------------
extern "C" void kernel_launch(void* const* d_in, const int* in_sizes, int n_in,
                              void* d_out, int out_size) {
    const float* x        = (const float*)d_in[0];
    const float* w_in     = (const float*)d_in[1];
    const float* b_in     = (const float*)d_in[2];
    const float* ln_in_g  = (const float*)d_in[3];
    const float* ln_in_b  = (const float*)d_in[4];
    const float* rb_ln_g  = (const float*)d_in[5];
    const float* rb_ln_b  = (const float*)d_in[6];
    const float* rb_w1    = (const float*)d_in[7];
    const float* rb_b1    = (const float*)d_in[8];
    const float* rb_w2    = (const float*)d_in[9];
    const float* rb_b2    = (const float*)d_in[10];
    const float* out_ln_g = (const float*)d_in[11];
    const float* out_ln_b = (const float*)d_in[12];
    const float* out_w1   = (const float*)d_in[13];
    const float* out_b1   = (const float*)d_in[14];
    const float* out_w2   = (const float*)d_in[15];
    const float* out_b2   = (const float*)d_in[16];
    float* out = (float*)d_out;

    float *p_h, *p_z, *p_zz, *p_a1;
    cudaGetSymbolAddress((void**)&p_h,  g_h);
    cudaGetSymbolAddress((void**)&p_z,  g_z);
    cudaGetSymbolAddress((void**)&p_zz, g_zz);
    cudaGetSymbolAddress((void**)&p_a1, g_a1);

    zero_counts<<<1, 64>>>();
    find_fronts<<<Bn, 256>>>(x);
    count_kernel<<<dim3(128, Bn), 256>>>(x);

    mlp_in<<<NTOK, 256>>>(w_in, b_in, ln_in_g, ln_in_b);

    for (int i = 0; i < 3; i++) {
        ln_kernel<<<NTOK, 256>>>(p_h, rb_ln_g + i * Hn, rb_ln_b + i * Hn, p_z);
        // z(512x256) @ w1(256x512) -> gelu -> zz(512x512)
        gemm_k<32, 64, 32, 4, 4, true, false>
            <<<dim3(512 / 64, NTOK / 32), 128>>>(p_z, rb_w1 + (size_t)i * Hn * 2 * Hn,
                                                 rb_b1 + i * 2 * Hn, p_zz, nullptr,
                                                 NTOK, 2 * Hn, Hn);
        // zz(512x512) @ w2(512x256) + h -> h(512x256)
        gemm_k<32, 32, 32, 2, 4, false, true>
            <<<dim3(256 / 32, NTOK / 32), 128>>>(p_zz, rb_w2 + (size_t)i * 2 * Hn * Hn,
                                                 rb_b2 + i * Hn, p_h, p_h,
                                                 NTOK, Hn, 2 * Hn);
    }

    ln_kernel<<<NTOK, 256>>>(p_h, out_ln_g, out_ln_b, p_z);
    // z(512x256) @ out_w1(256x128) -> gelu -> a1(512x128)
    gemm_k<32, 64, 32, 4, 4, true, false>
        <<<dim3(128 / 64, NTOK / 32), 128>>>(p_z, out_w1, out_b1, p_a1, nullptr,
                                             NTOK, 128, Hn);
    speed_kernel<<<4, 256>>>(out_w2, out_b2, out);
    assemble<<<1, NTOK>>>(out);
}

// round 2
// speedup vs baseline: 2.2330x; 2.2330x over previous
#include <cuda_runtime.h>
#include <math.h>

#define Xn 262144
#define Bn 64
#define Hn 256
#define THRF 1e-6f

__device__ __forceinline__ float gelu_f(float v) {
    return 0.5f * v * (1.0f + erff(v * 0.70710678118654752f));
}

// per-token LN stats for 4 tokens: warp t reduces buf[t][0..255]
__device__ __forceinline__ void ln_stats(const float buf[4][Hn], float* s_mu, float* s_rs) {
    int w = threadIdx.x >> 5, lane = threadIdx.x & 31;
    if (w < 4) {
        float s1 = 0.f, s2 = 0.f;
        #pragma unroll
        for (int j = 0; j < 8; j++) {
            float v = buf[w][lane + 32 * j];
            s1 += v;
            s2 = fmaf(v, v, s2);
        }
        #pragma unroll
        for (int o = 16; o; o >>= 1) {
            s1 += __shfl_xor_sync(0xffffffffu, s1, o);
            s2 += __shfl_xor_sync(0xffffffffu, s2, o);
        }
        if (lane == 0) {
            float mu = s1 * (1.f / 256.f);
            float var = fmaxf(s2 * (1.f / 256.f) - mu * mu, 0.f);
            s_mu[w] = mu;
            s_rs[w] = rsqrtf(var + 1e-5f);
        }
    }
    __syncthreads();
}

__global__ void __launch_bounds__(256) fused_all(
    const float* __restrict__ x,
    const float* __restrict__ w_in,  const float* __restrict__ b_in,
    const float* __restrict__ ln_in_g, const float* __restrict__ ln_in_b,
    const float* __restrict__ rb_ln_g, const float* __restrict__ rb_ln_b,
    const float* __restrict__ rb_w1,  const float* __restrict__ rb_b1,
    const float* __restrict__ rb_w2,  const float* __restrict__ rb_b2,
    const float* __restrict__ out_ln_g, const float* __restrict__ out_ln_b,
    const float* __restrict__ out_w1, const float* __restrict__ out_b1,
    const float* __restrict__ out_w2, const float* __restrict__ out_b2,
    float* __restrict__ out)
{
    const int tid = threadIdx.x;

    // ================= COUNT BLOCKS (128..191): one batch row each =================
    if (blockIdx.x >= 128) {
        int b = blockIdx.x - 128;
        const float*  d  = x + (size_t)b * 2 * Xn;
        const float4* d4 = (const float4*)d;
        int cnt = 0;
        #pragma unroll 4
        for (int i = tid; i < Xn / 4; i += 256) {
            float4 v = d4[i];
            float nx = 0.f;
            bool has_nx = (i < Xn / 4 - 1);
            if (has_nx) nx = d[4 * i + 4];
            cnt += (fabsf(v.x - v.y) > THRF);
            cnt += (fabsf(v.y - v.z) > THRF);
            cnt += (fabsf(v.z - v.w) > THRF);
            if (has_nx) cnt += (fabsf(v.w - nx) > THRF);
        }
        #pragma unroll
        for (int o = 16; o; o >>= 1) cnt += __shfl_xor_sync(0xffffffffu, cnt, o);
        __shared__ int cw[8];
        if ((tid & 31) == 0) cw[tid >> 5] = cnt;
        __syncthreads();
        if (tid == 0) {
            int s = 0;
            #pragma unroll
            for (int w = 0; w < 8; w++) s += cw[w];
            out[Bn * 48 + b] = (float)s;
        }
        return;
    }

    // ================= MLP BLOCKS (0..127): batch b, 4 tokens =================
    const int b     = blockIdx.x >> 1;
    const int kbase = (blockIdx.x & 1) * 4;
    const float* d  = x + (size_t)b * 2 * Xn;
    const float* cr = d + Xn;
    const int n = tid;

    __shared__ float s_h[4][Hn];       // residual state
    __shared__ float s_z[4][Hn];       // LN output / a1 scratch
    __shared__ float s_zz[4][2 * Hn];  // hidden / partial scratch
    __shared__ float s_mu[4], s_rs[4];
    __shared__ float s_tk[2][4];       // [0]=uL, [1]=uR per token
    __shared__ unsigned s_wm[8], s_vm[8];
    __shared__ int s_idx[8], s_non[8];
    __shared__ int s_nd, s_nn, s_done;

    // ---- phase 0: find first 8 discontinuities (ordered) ----
    if (tid == 0) { s_nd = 0; s_nn = 0; s_done = 0; }
    __syncthreads();
    for (int base = 0; base < Xn - 1; base += 256) {
        int i = base + tid;
        bool valid = (i < Xn - 1);
        bool disc = valid && (fabsf(d[i] - d[i + 1]) > THRF);
        unsigned m  = __ballot_sync(0xffffffffu, disc);
        unsigned vm = __ballot_sync(0xffffffffu, valid);
        if ((tid & 31) == 0) { s_wm[tid >> 5] = m; s_vm[tid >> 5] = vm; }
        __syncthreads();
        if (tid == 0) {
            for (int w = 0; w < 8 && s_nd < 8; w++) {
                unsigned mm = s_wm[w], vv = s_vm[w];
                int ib = base + w * 32;
                while (vv) {
                    int lane = __ffs(vv) - 1;
                    vv &= vv - 1;
                    int idx = ib + lane;
                    if ((mm >> lane) & 1u) {
                        if (s_nd < 8) {
                            s_idx[s_nd++] = idx;
                            if (s_nd >= 8) break;
                        }
                    } else {
                        if (s_nn < 8) s_non[s_nn++] = idx;
                    }
                }
            }
            if (s_nd >= 8) s_done = 1;
        }
        __syncthreads();
        if (s_done) break;
    }
    if (tid < 4) {
        int k = kbase + tid;
        int nd = s_nd;
        int i; float vf;
        if (k < nd) { i = s_idx[k]; vf = 1.0f; }
        else        { i = s_non[k - nd]; vf = 0.0f; }
        float uL = d[i], uR = d[i + 1];
        float fc = 0.5f * (cr[i] + cr[i + 1]);
        s_tk[0][tid] = uL;
        s_tk[1][tid] = uR;
        int base = b * 48;
        out[base + 16 + k] = uL;
        out[base + 24 + k] = uR;
        out[base + 32 + k] = fc;
        out[base + 40 + k] = vf;
    }
    __syncthreads();

    // ---- input layer: feats @ w_in + b_in -> LN -> gelu -> s_h ----
    {
        float wv[6];
        #pragma unroll
        for (int f = 0; f < 6; f++) wv[f] = w_in[f * Hn + n];
        float bi = b_in[n];
        #pragma unroll
        for (int t = 0; t < 4; t++) {
            float uL = s_tk[0][t], uR = s_tk[1][t];
            float df = uL - uR;
            float sg = (df > 0.f) ? 1.f : ((df < 0.f) ? -1.f : 0.f);
            float pre = bi;
            pre = fmaf(uL, wv[0], pre);
            pre = fmaf(uR, wv[1], pre);
            pre = fmaf(df, wv[2], pre);
            pre = fmaf(fabsf(df), wv[3], pre);
            pre = fmaf(0.5f * (uL + uR), wv[4], pre);
            pre = fmaf(sg, wv[5], pre);
            s_z[t][n] = pre;
        }
        __syncthreads();
        ln_stats(s_z, s_mu, s_rs);
        float lg = ln_in_g[n], lb = ln_in_b[n];
        #pragma unroll
        for (int t = 0; t < 4; t++)
            s_h[t][n] = gelu_f((s_z[t][n] - s_mu[t]) * s_rs[t] * lg + lb);
        __syncthreads();
    }

    // ---- 3 residual blocks ----
    for (int i = 0; i < 3; i++) {
        ln_stats(s_h, s_mu, s_rs);
        float g = rb_ln_g[i * Hn + n], bb = rb_ln_b[i * Hn + n];
        #pragma unroll
        for (int t = 0; t < 4; t++)
            s_z[t][n] = (s_h[t][n] - s_mu[t]) * s_rs[t] * g + bb;
        __syncthreads();

        // GEMM1: zz = gelu(z @ w1 + b1); thread owns cols 2n, 2n+1
        const float2* w1p = (const float2*)(rb_w1 + (size_t)i * Hn * 2 * Hn);
        const float*  b1p = rb_b1 + i * 2 * Hn;
        float acc0[4] = {0, 0, 0, 0}, acc1[4] = {0, 0, 0, 0};
        #pragma unroll 2
        for (int k0 = 0; k0 < Hn; k0 += 4) {
            float2 w0 = w1p[(k0 + 0) * Hn + n];
            float2 w1v = w1p[(k0 + 1) * Hn + n];
            float2 w2v = w1p[(k0 + 2) * Hn + n];
            float2 w3v = w1p[(k0 + 3) * Hn + n];
            #pragma unroll
            for (int t = 0; t < 4; t++) {
                float4 zv = *(const float4*)&s_z[t][k0];
                acc0[t] = fmaf(zv.x, w0.x, acc0[t]);  acc1[t] = fmaf(zv.x, w0.y, acc1[t]);
                acc0[t] = fmaf(zv.y, w1v.x, acc0[t]); acc1[t] = fmaf(zv.y, w1v.y, acc1[t]);
                acc0[t] = fmaf(zv.z, w2v.x, acc0[t]); acc1[t] = fmaf(zv.z, w2v.y, acc1[t]);
                acc0[t] = fmaf(zv.w, w3v.x, acc0[t]); acc1[t] = fmaf(zv.w, w3v.y, acc1[t]);
            }
        }
        {
            float bb0 = b1p[2 * n], bb1 = b1p[2 * n + 1];
            #pragma unroll
            for (int t = 0; t < 4; t++) {
                s_zz[t][2 * n]     = gelu_f(acc0[t] + bb0);
                s_zz[t][2 * n + 1] = gelu_f(acc1[t] + bb1);
            }
        }
        __syncthreads();

        // GEMM2: h += zz @ w2 + b2; thread owns col n
        const float* w2p = rb_w2 + (size_t)i * 2 * Hn * Hn;
        const float* b2p = rb_b2 + i * Hn;
        float a2[4] = {0, 0, 0, 0};
        #pragma unroll 2
        for (int k0 = 0; k0 < 2 * Hn; k0 += 4) {
            float wq0 = w2p[(k0 + 0) * Hn + n];
            float wq1 = w2p[(k0 + 1) * Hn + n];
            float wq2 = w2p[(k0 + 2) * Hn + n];
            float wq3 = w2p[(k0 + 3) * Hn + n];
            #pragma unroll
            for (int t = 0; t < 4; t++) {
                float4 zv = *(const float4*)&s_zz[t][k0];
                a2[t] = fmaf(zv.x, wq0, a2[t]);
                a2[t] = fmaf(zv.y, wq1, a2[t]);
                a2[t] = fmaf(zv.z, wq2, a2[t]);
                a2[t] = fmaf(zv.w, wq3, a2[t]);
            }
        }
        {
            float bq = b2p[n];
            #pragma unroll
            for (int t = 0; t < 4; t++)
                s_h[t][n] += a2[t] + bq;
        }
        __syncthreads();
    }

    // ---- output head ----
    ln_stats(s_h, s_mu, s_rs);
    {
        float og = out_ln_g[n], ob = out_ln_b[n];
        #pragma unroll
        for (int t = 0; t < 4; t++)
            s_z[t][n] = (s_h[t][n] - s_mu[t]) * s_rs[t] * og + ob;
    }
    __syncthreads();

    // a1 = gelu(z @ out_w1 + out_b1): 128 cols, split-K across thread halves
    {
        int c = n & 127;
        int half = n >> 7;
        int kstart = half * 128;
        float p[4] = {0, 0, 0, 0};
        #pragma unroll 2
        for (int k0 = kstart; k0 < kstart + 128; k0 += 4) {
            float w0 = out_w1[(k0 + 0) * 128 + c];
            float w1v = out_w1[(k0 + 1) * 128 + c];
            float w2v = out_w1[(k0 + 2) * 128 + c];
            float w3v = out_w1[(k0 + 3) * 128 + c];
            #pragma unroll
            for (int t = 0; t < 4; t++) {
                float4 zv = *(const float4*)&s_z[t][k0];
                p[t] = fmaf(zv.x, w0, p[t]);
                p[t] = fmaf(zv.y, w1v, p[t]);
                p[t] = fmaf(zv.z, w2v, p[t]);
                p[t] = fmaf(zv.w, w3v, p[t]);
            }
        }
        #pragma unroll
        for (int t = 0; t < 4; t++) s_zz[t][n] = p[t];  // partials at [c] and [c+128]
        __syncthreads();
        if (n < 128) {
            float bo = out_b1[n];
            #pragma unroll
            for (int t = 0; t < 4; t++)
                s_z[t][n] = gelu_f(s_zz[t][n] + s_zz[t][n + 128] + bo);
        }
        __syncthreads();
    }

    // speed = a1 @ out_w2 + out_b2: warp w handles (token w>>1, output col w&1)
    {
        int w = tid >> 5, lane = tid & 31;
        int t = w >> 1, cc = w & 1;
        float s = 0.f;
        s = fmaf(s_z[t][lane],      out_w2[lane * 2 + cc],        s);
        s = fmaf(s_z[t][lane + 32], out_w2[(lane + 32) * 2 + cc], s);
        s = fmaf(s_z[t][lane + 64], out_w2[(lane + 64) * 2 + cc], s);
        s = fmaf(s_z[t][lane + 96], out_w2[(lane + 96) * 2 + cc], s);
        #pragma unroll
        for (int o = 16; o; o >>= 1) s += __shfl_xor_sync(0xffffffffu, s, o);
        if (lane == 0)
            out[b * 48 + cc * 8 + (kbase + t)] = s + out_b2[cc];
    }
}

extern "C" void kernel_launch(void* const* d_in, const int* in_sizes, int n_in,
                              void* d_out, int out_size) {
    const float* x        = (const float*)d_in[0];
    const float* w_in     = (const float*)d_in[1];
    const float* b_in     = (const float*)d_in[2];
    const float* ln_in_g  = (const float*)d_in[3];
    const float* ln_in_b  = (const float*)d_in[4];
    const float* rb_ln_g  = (const float*)d_in[5];
    const float* rb_ln_b  = (const float*)d_in[6];
    const float* rb_w1    = (const float*)d_in[7];
    const float* rb_b1    = (const float*)d_in[8];
    const float* rb_w2    = (const float*)d_in[9];
    const float* rb_b2    = (const float*)d_in[10];
    const float* out_ln_g = (const float*)d_in[11];
    const float* out_ln_b = (const float*)d_in[12];
    const float* out_w1   = (const float*)d_in[13];
    const float* out_b1   = (const float*)d_in[14];
    const float* out_w2   = (const float*)d_in[15];
    const float* out_b2   = (const float*)d_in[16];
    float* out = (float*)d_out;

    fused_all<<<192, 256>>>(x, w_in, b_in, ln_in_g, ln_in_b,
                            rb_ln_g, rb_ln_b, rb_w1, rb_b1, rb_w2, rb_b2,
                            out_ln_g, out_ln_b, out_w1, out_b1, out_w2, out_b2,
                            out);
}

// round 3
// speedup vs baseline: 3.6063x; 1.6150x over previous
#include <cuda_runtime.h>
#include <math.h>

#define Xn 262144
#define Bn 64
#define Hn 256
#define THRF 1e-6f
#define NT 512            // threads per block
#define TILE_FLOATS 16384 // 64KB weight tile

__device__ __forceinline__ float gelu_f(float v) {
    return 0.5f * v * (1.0f + erff(v * 0.70710678118654752f));
}

__device__ __forceinline__ void cpa16(float* dst, const float* src) {
    unsigned d = (unsigned)__cvta_generic_to_shared(dst);
    asm volatile("cp.async.cg.shared.global [%0], [%1], 16;\n" :: "r"(d), "l"(src));
}
#define CPA_COMMIT() asm volatile("cp.async.commit_group;\n" ::)
#define CPA_WAIT(n)  asm volatile("cp.async.wait_group %0;\n" :: "n"(n))

// copy one 16384-float tile: 8 float4 per thread, coalesced
__device__ __forceinline__ void copy_tile(float* dst, const float* src, int tid) {
    #pragma unroll
    for (int j = 0; j < 8; j++)
        cpa16(dst + (tid + j * NT) * 4, src + (tid + j * NT) * 4);
    CPA_COMMIT();
}

// LN stats over 4 tokens x 256; warp t (t<4) reduces token t
__device__ __forceinline__ void ln_stats(const float* buf, float* s_mu, float* s_rs, int tid) {
    int w = tid >> 5, lane = tid & 31;
    if (w < 4) {
        float s1 = 0.f, s2 = 0.f;
        #pragma unroll
        for (int j = 0; j < 8; j++) {
            float v = buf[w * Hn + lane + 32 * j];
            s1 += v;
            s2 = fmaf(v, v, s2);
        }
        #pragma unroll
        for (int o = 16; o; o >>= 1) {
            s1 += __shfl_xor_sync(0xffffffffu, s1, o);
            s2 += __shfl_xor_sync(0xffffffffu, s2, o);
        }
        if (lane == 0) {
            float mu = s1 * (1.f / 256.f);
            float var = fmaxf(s2 * (1.f / 256.f) - mu * mu, 0.f);
            s_mu[w] = mu;
            s_rs[w] = rsqrtf(var + 1e-5f);
        }
    }
    __syncthreads();
}

__global__ void __launch_bounds__(NT, 1) fused_all(
    const float* __restrict__ x,
    const float* __restrict__ w_in,  const float* __restrict__ b_in,
    const float* __restrict__ ln_in_g, const float* __restrict__ ln_in_b,
    const float* __restrict__ rb_ln_g, const float* __restrict__ rb_ln_b,
    const float* __restrict__ rb_w1,  const float* __restrict__ rb_b1,
    const float* __restrict__ rb_w2,  const float* __restrict__ rb_b2,
    const float* __restrict__ out_ln_g, const float* __restrict__ out_ln_b,
    const float* __restrict__ out_w1, const float* __restrict__ out_b1,
    const float* __restrict__ out_w2, const float* __restrict__ out_b2,
    float* __restrict__ out)
{
    const int tid = threadIdx.x;

    // ============ COUNT BLOCKS (128..191): one batch row each ============
    if (blockIdx.x >= 128) {
        int b = blockIdx.x - 128;
        const float*  d  = x + (size_t)b * 2 * Xn;
        const float4* d4 = (const float4*)d;
        int cnt = 0;
        #pragma unroll 4
        for (int i = tid; i < Xn / 4; i += NT) {
            float4 v = d4[i];
            float nx = 0.f;
            bool has_nx = (i < Xn / 4 - 1);
            if (has_nx) nx = d[4 * i + 4];
            cnt += (fabsf(v.x - v.y) > THRF);
            cnt += (fabsf(v.y - v.z) > THRF);
            cnt += (fabsf(v.z - v.w) > THRF);
            if (has_nx) cnt += (fabsf(v.w - nx) > THRF);
        }
        #pragma unroll
        for (int o = 16; o; o >>= 1) cnt += __shfl_xor_sync(0xffffffffu, cnt, o);
        __shared__ int cw[16];
        if ((tid & 31) == 0) cw[tid >> 5] = cnt;
        __syncthreads();
        if (tid == 0) {
            int s = 0;
            #pragma unroll
            for (int w = 0; w < 16; w++) s += cw[w];
            out[Bn * 48 + b] = (float)s;
        }
        return;
    }

    // ============ MLP BLOCKS (0..127): batch b, 4 tokens ============
    const int b     = blockIdx.x >> 1;
    const int kbase = (blockIdx.x & 1) * 4;
    const float* d  = x + (size_t)b * 2 * Xn;
    const float* cr = d + Xn;

    extern __shared__ float smem[];
    float* wb0  = smem;                 // 16384 floats
    float* wb1  = smem + TILE_FLOATS;   // 16384 floats
    float* s_h  = smem + 2 * TILE_FLOATS;          // 4*256
    float* s_zv = s_h + 4 * Hn;                    // 4*256
    float* s_zz = s_zv + 4 * Hn;                   // 4*512

    __shared__ float s_mu[4], s_rs[4];
    __shared__ float s_tk[2][4];
    __shared__ unsigned s_wm[16], s_vm[16];
    __shared__ int s_idx[8], s_non[8];
    __shared__ int s_nd, s_nn, s_done;

    // ---- phase 0: find first 8 discontinuities (ordered) ----
    if (tid == 0) { s_nd = 0; s_nn = 0; s_done = 0; }
    __syncthreads();
    for (int base = 0; base < Xn - 1; base += NT) {
        int i = base + tid;
        bool valid = (i < Xn - 1);
        bool disc = valid && (fabsf(d[i] - d[i + 1]) > THRF);
        unsigned m  = __ballot_sync(0xffffffffu, disc);
        unsigned vm = __ballot_sync(0xffffffffu, valid);
        if ((tid & 31) == 0) { s_wm[tid >> 5] = m; s_vm[tid >> 5] = vm; }
        __syncthreads();
        if (tid == 0) {
            for (int w = 0; w < 16 && s_nd < 8; w++) {
                unsigned mm = s_wm[w], vv = s_vm[w];
                int ib = base + w * 32;
                while (vv) {
                    int lane = __ffs(vv) - 1;
                    vv &= vv - 1;
                    int idx = ib + lane;
                    if ((mm >> lane) & 1u) {
                        if (s_nd < 8) {
                            s_idx[s_nd++] = idx;
                            if (s_nd >= 8) break;
                        }
                    } else {
                        if (s_nn < 8) s_non[s_nn++] = idx;
                    }
                }
            }
            if (s_nd >= 8) s_done = 1;
        }
        __syncthreads();
        if (s_done) break;
    }
    if (tid < 4) {
        int k = kbase + tid;
        int nd = s_nd;
        int i; float vf;
        if (k < nd) { i = s_idx[k]; vf = 1.0f; }
        else        { i = s_non[k - nd]; vf = 0.0f; }
        float uL = d[i], uR = d[i + 1];
        float fc = 0.5f * (cr[i] + cr[i + 1]);
        s_tk[0][tid] = uL;
        s_tk[1][tid] = uR;
        int base = b * 48;
        out[base + 16 + k] = uL;
        out[base + 24 + k] = uR;
        out[base + 32 + k] = fc;
        out[base + 40 + k] = vf;
    }
    __syncthreads();

    // ---- input layer (threads < 256 active) ----
    if (tid < Hn) {
        int n = tid;
        float wv[6];
        #pragma unroll
        for (int f = 0; f < 6; f++) wv[f] = w_in[f * Hn + n];
        float bi = b_in[n];
        #pragma unroll
        for (int t = 0; t < 4; t++) {
            float uL = s_tk[0][t], uR = s_tk[1][t];
            float df = uL - uR;
            float sg = (df > 0.f) ? 1.f : ((df < 0.f) ? -1.f : 0.f);
            float pre = bi;
            pre = fmaf(uL, wv[0], pre);
            pre = fmaf(uR, wv[1], pre);
            pre = fmaf(df, wv[2], pre);
            pre = fmaf(fabsf(df), wv[3], pre);
            pre = fmaf(0.5f * (uL + uR), wv[4], pre);
            pre = fmaf(sg, wv[5], pre);
            s_zv[t * Hn + n] = pre;
        }
    }
    __syncthreads();
    ln_stats(s_zv, s_mu, s_rs, tid);
    if (tid < Hn) {
        float lg = ln_in_g[tid], lb = ln_in_b[tid];
        #pragma unroll
        for (int t = 0; t < 4; t++)
            s_h[t * Hn + tid] = gelu_f((s_zv[t * Hn + tid] - s_mu[t]) * s_rs[t] * lg + lb);
    }
    __syncthreads();

    // ---- 3 residual blocks (weights staged via cp.async double-buffer) ----
    for (int i = 0; i < 3; i++) {
        ln_stats(s_h, s_mu, s_rs, tid);
        if (tid < Hn) {
            float g = rb_ln_g[i * Hn + tid], bb = rb_ln_b[i * Hn + tid];
            #pragma unroll
            for (int t = 0; t < 4; t++)
                s_zv[t * Hn + tid] = (s_h[t * Hn + tid] - s_mu[t]) * s_rs[t] * g + bb;
        }
        __syncthreads();

        // ===== GEMM1: zz[t][c] = gelu( sum_k z[t][k]*W1[k][c] + b1[c] ), c = tid (512 cols)
        {
            const float* W1 = rb_w1 + (size_t)i * Hn * 2 * Hn; // [256][512]
            float acc0 = 0, acc1 = 0, acc2 = 0, acc3 = 0;
            copy_tile(wb0, W1, tid);  // tile 0 (32 rows x 512)
            #pragma unroll
            for (int t8 = 0; t8 < 8; t8++) {
                float* cur = (t8 & 1) ? wb1 : wb0;
                float* nxt = (t8 & 1) ? wb0 : wb1;
                if (t8 + 1 < 8) { copy_tile(nxt, W1 + (t8 + 1) * TILE_FLOATS, tid); CPA_WAIT(1); }
                else            { CPA_WAIT(0); }
                __syncthreads();
                int k0 = t8 * 32;
                #pragma unroll
                for (int kk = 0; kk < 8; kk++) {
                    float4 z0 = *(const float4*)&s_zv[0 * Hn + k0 + kk * 4];
                    float4 z1 = *(const float4*)&s_zv[1 * Hn + k0 + kk * 4];
                    float4 z2 = *(const float4*)&s_zv[2 * Hn + k0 + kk * 4];
                    float4 z3 = *(const float4*)&s_zv[3 * Hn + k0 + kk * 4];
                    float w0 = cur[(kk * 4 + 0) * 512 + tid];
                    float w1v = cur[(kk * 4 + 1) * 512 + tid];
                    float w2v = cur[(kk * 4 + 2) * 512 + tid];
                    float w3v = cur[(kk * 4 + 3) * 512 + tid];
                    acc0 = fmaf(z0.x, w0, acc0); acc0 = fmaf(z0.y, w1v, acc0);
                    acc0 = fmaf(z0.z, w2v, acc0); acc0 = fmaf(z0.w, w3v, acc0);
                    acc1 = fmaf(z1.x, w0, acc1); acc1 = fmaf(z1.y, w1v, acc1);
                    acc1 = fmaf(z1.z, w2v, acc1); acc1 = fmaf(z1.w, w3v, acc1);
                    acc2 = fmaf(z2.x, w0, acc2); acc2 = fmaf(z2.y, w1v, acc2);
                    acc2 = fmaf(z2.z, w2v, acc2); acc2 = fmaf(z2.w, w3v, acc2);
                    acc3 = fmaf(z3.x, w0, acc3); acc3 = fmaf(z3.y, w1v, acc3);
                    acc3 = fmaf(z3.z, w2v, acc3); acc3 = fmaf(z3.w, w3v, acc3);
                }
                __syncthreads();
            }
            float bb = rb_b1[i * 2 * Hn + tid];
            s_zz[0 * 512 + tid] = gelu_f(acc0 + bb);
            s_zz[1 * 512 + tid] = gelu_f(acc1 + bb);
            s_zz[2 * 512 + tid] = gelu_f(acc2 + bb);
            s_zz[3 * 512 + tid] = gelu_f(acc3 + bb);
            __syncthreads();
        }

        // ===== GEMM2: h[t][c] += sum_k zz[t][k]*W2[k][c] + b2[c]; split-K by 2
        {
            const float* W2 = rb_w2 + (size_t)i * 2 * Hn * Hn; // [512][256]
            const int col = tid & 255, half = tid >> 8;
            float acc0 = 0, acc1 = 0, acc2 = 0, acc3 = 0;
            copy_tile(wb0, W2, tid);  // tile 0 (64 rows x 256)
            #pragma unroll
            for (int t8 = 0; t8 < 8; t8++) {
                float* cur = (t8 & 1) ? wb1 : wb0;
                float* nxt = (t8 & 1) ? wb0 : wb1;
                if (t8 + 1 < 8) { copy_tile(nxt, W2 + (t8 + 1) * TILE_FLOATS, tid); CPA_WAIT(1); }
                else            { CPA_WAIT(0); }
                __syncthreads();
                int klocal = half * 32;            // within 64-row tile
                int kglob  = t8 * 64 + klocal;     // zz index
                #pragma unroll
                for (int kk = 0; kk < 8; kk++) {
                    float4 z0 = *(const float4*)&s_zz[0 * 512 + kglob + kk * 4];
                    float4 z1 = *(const float4*)&s_zz[1 * 512 + kglob + kk * 4];
                    float4 z2 = *(const float4*)&s_zz[2 * 512 + kglob + kk * 4];
                    float4 z3 = *(const float4*)&s_zz[3 * 512 + kglob + kk * 4];
                    float w0 = cur[(klocal + kk * 4 + 0) * 256 + col];
                    float w1v = cur[(klocal + kk * 4 + 1) * 256 + col];
                    float w2v = cur[(klocal + kk * 4 + 2) * 256 + col];
                    float w3v = cur[(klocal + kk * 4 + 3) * 256 + col];
                    acc0 = fmaf(z0.x, w0, acc0); acc0 = fmaf(z0.y, w1v, acc0);
                    acc0 = fmaf(z0.z, w2v, acc0); acc0 = fmaf(z0.w, w3v, acc0);
                    acc1 = fmaf(z1.x, w0, acc1); acc1 = fmaf(z1.y, w1v, acc1);
                    acc1 = fmaf(z1.z, w2v, acc1); acc1 = fmaf(z1.w, w3v, acc1);
                    acc2 = fmaf(z2.x, w0, acc2); acc2 = fmaf(z2.y, w1v, acc2);
                    acc2 = fmaf(z2.z, w2v, acc2); acc2 = fmaf(z2.w, w3v, acc2);
                    acc3 = fmaf(z3.x, w0, acc3); acc3 = fmaf(z3.y, w1v, acc3);
                    acc3 = fmaf(z3.z, w2v, acc3); acc3 = fmaf(z3.w, w3v, acc3);
                }
                __syncthreads();
            }
            if (half == 0) {
                s_zv[0 * Hn + col] = acc0;
                s_zv[1 * Hn + col] = acc1;
                s_zv[2 * Hn + col] = acc2;
                s_zv[3 * Hn + col] = acc3;
            }
            __syncthreads();
            if (half == 1) {
                float bq = rb_b2[i * Hn + col];
                s_h[0 * Hn + col] += s_zv[0 * Hn + col] + acc0 + bq;
                s_h[1 * Hn + col] += s_zv[1 * Hn + col] + acc1 + bq;
                s_h[2 * Hn + col] += s_zv[2 * Hn + col] + acc2 + bq;
                s_h[3 * Hn + col] += s_zv[3 * Hn + col] + acc3 + bq;
            }
            __syncthreads();
        }
    }

    // ---- output head ----
    ln_stats(s_h, s_mu, s_rs, tid);
    if (tid < Hn) {
        float og = out_ln_g[tid], ob = out_ln_b[tid];
        #pragma unroll
        for (int t = 0; t < 4; t++)
            s_zv[t * Hn + tid] = (s_h[t * Hn + tid] - s_mu[t]) * s_rs[t] * og + ob;
    }
    __syncthreads();

    // a1 = gelu(z @ out_w1 + b1): out_w1 [256][128] = 32768 floats staged whole
    {
        #pragma unroll
        for (int j = 0; j < 16; j++)
            cpa16(wb0 + (tid + j * NT) * 4, out_w1 + (tid + j * NT) * 4);
        CPA_COMMIT();
        CPA_WAIT(0);
        __syncthreads();
        const int col = tid & 127, kq = tid >> 7; // 4-way split-K (64 each)
        int kb = kq * 64;
        float p0 = 0, p1 = 0, p2 = 0, p3 = 0;
        #pragma unroll
        for (int kk = 0; kk < 16; kk++) {
            float4 z0 = *(const float4*)&s_zv[0 * Hn + kb + kk * 4];
            float4 z1 = *(const float4*)&s_zv[1 * Hn + kb + kk * 4];
            float4 z2 = *(const float4*)&s_zv[2 * Hn + kb + kk * 4];
            float4 z3 = *(const float4*)&s_zv[3 * Hn + kb + kk * 4];
            float w0 = wb0[(kb + kk * 4 + 0) * 128 + col];
            float w1v = wb0[(kb + kk * 4 + 1) * 128 + col];
            float w2v = wb0[(kb + kk * 4 + 2) * 128 + col];
            float w3v = wb0[(kb + kk * 4 + 3) * 128 + col];
            p0 = fmaf(z0.x, w0, p0); p0 = fmaf(z0.y, w1v, p0);
            p0 = fmaf(z0.z, w2v, p0); p0 = fmaf(z0.w, w3v, p0);
            p1 = fmaf(z1.x, w0, p1); p1 = fmaf(z1.y, w1v, p1);
            p1 = fmaf(z1.z, w2v, p1); p1 = fmaf(z1.w, w3v, p1);
            p2 = fmaf(z2.x, w0, p2); p2 = fmaf(z2.y, w1v, p2);
            p2 = fmaf(z2.z, w2v, p2); p2 = fmaf(z2.w, w3v, p2);
            p3 = fmaf(z3.x, w0, p3); p3 = fmaf(z3.y, w1v, p3);
            p3 = fmaf(z3.z, w2v, p3); p3 = fmaf(z3.w, w3v, p3);
        }
        s_zz[0 * 512 + kq * 128 + col] = p0;
        s_zz[1 * 512 + kq * 128 + col] = p1;
        s_zz[2 * 512 + kq * 128 + col] = p2;
        s_zz[3 * 512 + kq * 128 + col] = p3;
        __syncthreads();
        if (tid < 128) {
            float bo = out_b1[tid];
            #pragma unroll
            for (int t = 0; t < 4; t++) {
                float s = s_zz[t * 512 + tid] + s_zz[t * 512 + 128 + tid]
                        + s_zz[t * 512 + 256 + tid] + s_zz[t * 512 + 384 + tid] + bo;
                s_zv[t * Hn + tid] = gelu_f(s);
            }
        }
        __syncthreads();
    }

    // speed = a1 @ out_w2 + out_b2: warps 0..7 -> (token, col)
    {
        int w = tid >> 5, lane = tid & 31;
        if (w < 8) {
            int t = w >> 1, cc = w & 1;
            float s = 0.f;
            s = fmaf(s_zv[t * Hn + lane],      out_w2[lane * 2 + cc],        s);
            s = fmaf(s_zv[t * Hn + lane + 32], out_w2[(lane + 32) * 2 + cc], s);
            s = fmaf(s_zv[t * Hn + lane + 64], out_w2[(lane + 64) * 2 + cc], s);
            s = fmaf(s_zv[t * Hn + lane + 96], out_w2[(lane + 96) * 2 + cc], s);
            #pragma unroll
            for (int o = 16; o; o >>= 1) s += __shfl_xor_sync(0xffffffffu, s, o);
            if (lane == 0)
                out[b * 48 + cc * 8 + (kbase + t)] = s + out_b2[cc];
        }
    }
}

extern "C" void kernel_launch(void* const* d_in, const int* in_sizes, int n_in,
                              void* d_out, int out_size) {
    const float* x        = (const float*)d_in[0];
    const float* w_in     = (const float*)d_in[1];
    const float* b_in     = (const float*)d_in[2];
    const float* ln_in_g  = (const float*)d_in[3];
    const float* ln_in_b  = (const float*)d_in[4];
    const float* rb_ln_g  = (const float*)d_in[5];
    const float* rb_ln_b  = (const float*)d_in[6];
    const float* rb_w1    = (const float*)d_in[7];
    const float* rb_b1    = (const float*)d_in[8];
    const float* rb_w2    = (const float*)d_in[9];
    const float* rb_b2    = (const float*)d_in[10];
    const float* out_ln_g = (const float*)d_in[11];
    const float* out_ln_b = (const float*)d_in[12];
    const float* out_w1   = (const float*)d_in[13];
    const float* out_b1   = (const float*)d_in[14];
    const float* out_w2   = (const float*)d_in[15];
    const float* out_b2   = (const float*)d_in[16];
    float* out = (float*)d_out;

    // dynamic smem: 2 tiles (32768) + h (1024) + z (1024) + zz (2048) floats
    const int smem_bytes = (2 * TILE_FLOATS + 4 * Hn + 4 * Hn + 4 * 512) * sizeof(float);
    cudaFuncSetAttribute(fused_all, cudaFuncAttributeMaxDynamicSharedMemorySize, smem_bytes);

    fused_all<<<192, NT, smem_bytes>>>(x, w_in, b_in, ln_in_g, ln_in_b,
                                       rb_ln_g, rb_ln_b, rb_w1, rb_b1, rb_w2, rb_b2,
                                       out_ln_g, out_ln_b, out_w1, out_b1, out_w2, out_b2,
                                       out);
}